// round 2
// baseline (speedup 1.0000x reference)
#include <cuda_runtime.h>

// Problem constants
#define EPSILON 1e-4f
#define ITERS   100
#define MARG    0.001953125f   // 1/512

#define ROWS 32                 // rows of K per sinkhorn CTA
#define NBLK 16                 // 512 / 32
#define NCTA 128                // 8 batches * 16 blocks
#define STH  512                // threads per sinkhorn CTA

// Scratch (static device globals — no allocation)
__device__ float    gA[8 * 512 * 32];                 // out-side projections
__device__ float    gB[8 * 512 * 32];                 // in-side projections
__device__ float    gPartial[2][8][16][512];          // double-buffered col partial sums
__device__ float    gSpart[8][16];                    // per-block cost sums (deterministic)
__device__ unsigned gBar;                             // grid barrier counter

// -------- software grid barrier (all 128 CTAs are resident: 1 CTA/SM) --------
__device__ __forceinline__ void grid_bar(unsigned target) {
    __syncthreads();
    if (threadIdx.x == 0) {
        __threadfence();                 // publish this CTA's global writes
        atomicAdd(&gBar, 1u);
        while (*(volatile unsigned*)&gBar < target) { }
        __threadfence();                 // acquire
    }
    __syncthreads();
}

// ---------------- prep: a = (out+pos)@W_out + b_out ; b = where(mask,pad,in)@W_in + b_in
__global__ void __launch_bounds__(256) prep_kernel(
    const float* __restrict__ in_emb, const int* __restrict__ mask,
    const float* __restrict__ out_emb, const float* __restrict__ pad,
    const float* __restrict__ pos, const float* __restrict__ W_in,
    const float* __restrict__ b_in, const float* __restrict__ W_out,
    const float* __restrict__ b_out)
{
    __shared__ float Ws[256 * 32];     // 32 KB
    __shared__ float xS[8][256];       // 8 KB
    int tid = threadIdx.x;
    if (blockIdx.x == 0 && tid == 0) gBar = 0u;   // reset barrier for this launch

    bool isA = blockIdx.x < 512;                  // 512 CTAs each side, 8 rows/CTA
    int rowbase = (blockIdx.x & 511) * 8;         // row in [0,4096)
    const float* W    = isA ? W_out : W_in;
    const float* bias = isA ? b_out : b_in;

    for (int k = tid; k < 256 * 32; k += 256) Ws[k] = W[k];
    for (int k = tid; k < 8 * 256; k += 256) {
        int r = rowbase + (k >> 8);
        int d = k & 255;
        int n = r & 511;
        float v;
        if (isA) v = out_emb[r * 256 + d] + pos[n * 256 + d];
        else     v = (mask[r] != 0) ? pad[d] : in_emb[r * 256 + d];
        xS[k >> 8][d] = v;
    }
    __syncthreads();

    int w = tid >> 5, lane = tid & 31;            // warp w computes local row w, lane = out col
    float acc = bias[lane];
#pragma unroll 8
    for (int d = 0; d < 256; d++)
        acc = fmaf(xS[w][d], Ws[d * 32 + lane], acc);
    float* dst = isA ? gA : gB;
    dst[(rowbase + w) * 32 + lane] = acc;
}

// ---------------- persistent Sinkhorn kernel ----------------
// SMEM float offsets
#define SM_AS 16384                    // after Ks[32*512]
#define SM_VS (16384 + 1024)
#define SM_US (SM_VS + 512)
#define SM_BB (SM_US + 32)
#define SMEM_FLOATS (SM_BB + 16384)    // 34336 floats = 137344 bytes

__global__ void __launch_bounds__(STH, 1) sinkhorn_kernel(float* __restrict__ out)
{
    extern __shared__ float sm[];
    float* Ks  = sm;                   // [32][512] K block
    float* aS  = sm + SM_AS;           // [32][32]
    float* vS  = sm + SM_VS;           // [512]
    float* uS  = sm + SM_US;           // [32]
    float* bbS = sm + SM_BB;           // [512][32] swizzled (prologue only)
    __shared__ float red[16];

    int tid = threadIdx.x;
    int b   = blockIdx.x >> 4;
    int blk = blockIdx.x & 15;
    int i0  = blk * ROWS;

    // ---- prologue: stage a rows and all b rows of this batch ----
    const float* Ab = gA + (b * 512 + i0) * 32;
    const float* Bb = gB + b * 512 * 32;
    for (int k = tid; k < ROWS * 32; k += STH) aS[k] = Ab[k];
    for (int k = tid; k < 512 * 32; k += STH) {
        int j = k >> 5, m = k & 31;
        bbS[(j << 5) + (m ^ (j & 31))] = Bb[k];    // swizzle: conflict-free readback
    }
    __syncthreads();

    // b-row for this thread's column into registers (conflict-free thanks to swizzle)
    float bb[32];
#pragma unroll
    for (int m = 0; m < 32; m++) bb[m] = bbS[(tid << 5) + (m ^ (tid & 31))];

    // ---- raw L1 cost block + local sum ----
    float localsum = 0.f;
    for (int i = 0; i < ROWS; i++) {
        const float4* a4 = (const float4*)(aS + (i << 5));
        float acc = 0.f;
#pragma unroll
        for (int m4 = 0; m4 < 8; m4++) {
            float4 av = a4[m4];
            acc += fabsf(av.x - bb[4 * m4 + 0]) + fabsf(av.y - bb[4 * m4 + 1])
                 + fabsf(av.z - bb[4 * m4 + 2]) + fabsf(av.w - bb[4 * m4 + 3]);
        }
        Ks[(i << 9) + tid] = acc;
        localsum += acc;
    }

    // deterministic block sum -> gSpart[b][blk]
#pragma unroll
    for (int off = 16; off; off >>= 1)
        localsum += __shfl_xor_sync(0xffffffffu, localsum, off);
    if ((tid & 31) == 0) red[tid >> 5] = localsum;
    __syncthreads();
    if (tid == 0) {
        float s = 0.f;
#pragma unroll
        for (int k = 0; k < 16; k++) s += red[k];
        gSpart[b][blk] = s;
    }

    grid_bar(NCTA);    // generation 1

    // deterministic batch sum, then K = exp(-C / (eps * S))
    float Ssum = 0.f;
#pragma unroll
    for (int k = 0; k < 16; k++) Ssum += __ldcg(&gSpart[b][k]);
    float alpha = -1.0f / (EPSILON * Ssum);

    float kr[32];      // this thread's K column, kept in registers
#pragma unroll
    for (int i = 0; i < 32; i++) {
        float kv = __expf(Ks[(i << 9) + tid] * alpha);
        Ks[(i << 9) + tid] = kv;
        kr[i] = kv;
    }
    __syncthreads();

    // ---- main loop: u = marg/(K v), col-partials for v ----
    int w = tid >> 5, lane = tid & 31;
    unsigned gen = 2;
    for (int p = 0; p < ITERS; p++) {
        float vj;
        if (p == 0) {
            vj = 1.0f;                                    // v^0 = exp(0)
        } else {
            const float* pp = &gPartial[(p - 1) & 1][b][0][tid];
            float cs = 0.f;
#pragma unroll
            for (int k = 0; k < NBLK; k++) cs += __ldcg(pp + (k << 9));
            vj = MARG / cs;
        }
        vS[tid] = vj;
        __syncthreads();

        // hoist this lane's 16 v values
        float vr[16];
#pragma unroll
        for (int jj = 0; jj < 16; jj++) vr[jj] = vS[(jj << 5) + lane];

        // 2 rows per warp: u_i = marg / sum_j K_ij v_j
#pragma unroll
        for (int r = 0; r < 2; r++) {
            int i = (w << 1) + r;
            float s = 0.f;
#pragma unroll
            for (int jj = 0; jj < 16; jj++)
                s = fmaf(Ks[(i << 9) + (jj << 5) + lane], vr[jj], s);
#pragma unroll
            for (int off = 16; off; off >>= 1)
                s += __shfl_xor_sync(0xffffffffu, s, off);
            if (lane == 0) uS[i] = MARG / s;
        }
        __syncthreads();

        // column partial from registers: c_j = sum_{i in block} K_ij u_i
        float c = 0.f;
#pragma unroll
        for (int i = 0; i < 32; i++) c = fmaf(kr[i], uS[i], c);
        gPartial[p & 1][b][blk][tid] = c;

        grid_bar(NCTA * gen); gen++;
    }

    // ---- epilogue: v^100 then P = K * u * v ----
    {
        const float* pp = &gPartial[(ITERS - 1) & 1][b][0][tid];
        float cs = 0.f;
#pragma unroll
        for (int k = 0; k < NBLK; k++) cs += __ldcg(pp + (k << 9));
        float vj = MARG / cs;
        float* o = out + ((size_t)(b * 512 + i0)) * 512 + tid;
#pragma unroll
        for (int i = 0; i < 32; i++)
            o[(size_t)i * 512] = kr[i] * uS[i] * vj;
    }
}

extern "C" void kernel_launch(void* const* d_in, const int* in_sizes, int n_in,
                              void* d_out, int out_size) {
    const float* in_emb  = (const float*)d_in[0];
    const int*   mask    = (const int*)d_in[1];
    const float* out_emb = (const float*)d_in[2];
    const float* pad     = (const float*)d_in[3];
    const float* pos     = (const float*)d_in[4];
    const float* W_in    = (const float*)d_in[5];
    const float* b_in    = (const float*)d_in[6];
    const float* W_out   = (const float*)d_in[7];
    const float* b_out   = (const float*)d_in[8];

    cudaFuncSetAttribute(sinkhorn_kernel,
                         cudaFuncAttributeMaxDynamicSharedMemorySize,
                         SMEM_FLOATS * 4);

    prep_kernel<<<1024, 256>>>(in_emb, mask, out_emb, pad, pos,
                               W_in, b_in, W_out, b_out);
    sinkhorn_kernel<<<NCTA, STH, SMEM_FLOATS * 4>>>((float*)d_out);
}